// round 1
// baseline (speedup 1.0000x reference)
#include <cuda_runtime.h>
#include <cuda_bf16.h>
#include <math.h>

#define BB 2
#define HH 128
#define WW 128
#define HW (HH*WW)
#define DIM 128
#define NH 8
#define HD 16
#define KA2 9

// Scratch (device globals; allocation-free rule)
__device__ float g_E[BB * 19 * HW];          // extra channels: 0-7 cond, 8 lpan, 9 pan, 10 pan-lpan, 11-18 ms
__device__ float g_OUT[BB * 640 * HW];       // 0-127 q(scaled), 128-255 k_pan, 256-383 v_pan, 384-511 k_ms, 512-639 v_ms
__device__ float g_ATT[BB * 2 * DIM * HW];   // attention output, (b, s, c, hw)

// ---------------------------------------------------------------------------
// Pack the non-x input channels
// ---------------------------------------------------------------------------
__global__ void pack_kernel(const float* __restrict__ ms,
                            const float* __restrict__ lpan,
                            const float* __restrict__ pan,
                            const float* __restrict__ s)
{
    int idx = blockIdx.x * blockDim.x + threadIdx.x;
    if (idx >= BB * HW) return;
    int b = idx / HW;
    int p = idx % HW;
    float sv = s[b];
    float lp = lpan[b * HW + p];
    float pn = pan[b * HW + p];
    float* Eb = g_E + b * 19 * HW;
#pragma unroll
    for (int c = 0; c < 8; c++) {
        float m = ms[(b * 8 + c) * HW + p];
        Eb[c * HW + p]        = lp * (1.0f - sv) + m * sv;   // cond
        Eb[(11 + c) * HW + p] = m;                            // ms copy
    }
    Eb[8 * HW + p]  = lp;
    Eb[9 * HW + p]  = pn;
    Eb[10 * HW + p] = pn - lp;
}

// ---------------------------------------------------------------------------
// Generic 3x3 conv: input = [x(128 ch) | extras from g_E starting at extra_base]
// Output tile: 16x16 pixels x 32 output channels per block.
// Thread: 2x2 px x 8 oc register block.
// ---------------------------------------------------------------------------
__global__ __launch_bounds__(256) void conv3x3_kernel(
    const float* __restrict__ x,
    const float* __restrict__ wt,
    const float* __restrict__ bias,
    int cin, int extra_base, int out_off, float scale)
{
    __shared__ float s_in[4][18 * 20];
    __shared__ float s_w[32][4][9];

    int b   = blockIdx.z;
    int ty0 = (blockIdx.x >> 3) * 16;
    int tx0 = (blockIdx.x & 7) * 16;
    int ocb = blockIdx.y * 32;
    int t   = threadIdx.x;
    int pg  = t & 63;            // 64 pixel groups (2x2 each)
    int og  = t >> 6;            // 4 oc groups of 8
    int gy  = (pg >> 3) * 2;
    int gx  = (pg & 7) * 2;

    const float* xb = x + b * 128 * HW;
    const float* Eb = g_E + b * 19 * HW;

    float acc[2][2][8];
#pragma unroll
    for (int a = 0; a < 2; a++)
#pragma unroll
        for (int bb2 = 0; bb2 < 2; bb2++)
#pragma unroll
            for (int o = 0; o < 8; o++) acc[a][bb2][o] = 0.0f;

    for (int c0 = 0; c0 < cin; c0 += 4) {
        // load input tile (4 channels x 18x18, zero-padded)
        for (int i = t; i < 4 * 18 * 18; i += 256) {
            int cc = i / 324;
            int r  = i % 324;
            int iy = r / 18, ix = r % 18;
            int c  = c0 + cc;
            int yy = ty0 - 1 + iy, xx = tx0 - 1 + ix;
            float v = 0.0f;
            if (c < cin && yy >= 0 && yy < HH && xx >= 0 && xx < WW) {
                const float* src = (c < 128) ? (xb + c * HW)
                                             : (Eb + (extra_base + (c - 128)) * HW);
                v = src[yy * WW + xx];
            }
            s_in[cc][iy * 20 + ix] = v;
        }
        // load weights (32 oc x 4 cin x 9)
        for (int i = t; i < 32 * 4 * 9; i += 256) {
            int o  = i / 36;
            int r  = i % 36;
            int cc = r / 9;
            int k  = r % 9;
            int c  = c0 + cc;
            s_w[o][cc][k] = (c < cin) ? wt[((ocb + o) * cin + c) * 9 + k] : 0.0f;
        }
        __syncthreads();

#pragma unroll
        for (int cc = 0; cc < 4; cc++) {
            float in[4][4];
#pragma unroll
            for (int yy = 0; yy < 4; yy++)
#pragma unroll
                for (int xx = 0; xx < 4; xx++)
                    in[yy][xx] = s_in[cc][(gy + yy) * 20 + gx + xx];
#pragma unroll
            for (int o = 0; o < 8; o++) {
                float wv[9];
#pragma unroll
                for (int k = 0; k < 9; k++) wv[k] = s_w[og * 8 + o][cc][k];
#pragma unroll
                for (int py = 0; py < 2; py++)
#pragma unroll
                    for (int px = 0; px < 2; px++) {
                        float a = acc[py][px][o];
#pragma unroll
                        for (int ky = 0; ky < 3; ky++)
#pragma unroll
                            for (int kx = 0; kx < 3; kx++)
                                a += wv[ky * 3 + kx] * in[py + ky][px + kx];
                        acc[py][px][o] = a;
                    }
            }
        }
        __syncthreads();
    }

#pragma unroll
    for (int o = 0; o < 8; o++) {
        int oc = ocb + og * 8 + o;
        float bs = bias[oc];
#pragma unroll
        for (int py = 0; py < 2; py++)
#pragma unroll
            for (int px = 0; px < 2; px++) {
                int y = ty0 + gy + py;
                int xo = tx0 + gx + px;
                g_OUT[(b * 640 + out_off + oc) * HW + y * WW + xo] =
                    (acc[py][px][o] + bs) * scale;
            }
    }
}

// ---------------------------------------------------------------------------
// Fused depthwise conv (16 groups x 9 filters) + logits + softmax + V
// One block per (b, s, head, 16x16 tile). One thread per pixel.
// ---------------------------------------------------------------------------
__global__ __launch_bounds__(256) void attn_kernel(const float* __restrict__ dep_w,
                                                   const float* __restrict__ dep_b)
{
    __shared__ float s_raw[16][18 * 20];
    __shared__ float s_dw[144][9];
    __shared__ float s_db[144];

    int b    = blockIdx.z;
    int sn   = blockIdx.y;
    int sidx = sn >> 3;
    int n    = sn & 7;
    int ty0  = (blockIdx.x >> 3) * 16;
    int tx0  = (blockIdx.x & 7) * 16;
    int t    = threadIdx.x;
    int ly   = t >> 4, lx = t & 15;
    int Y    = ty0 + ly, X = tx0 + lx;

    for (int i = t; i < 144 * 9; i += 256) s_dw[i / 9][i % 9] = dep_w[i];
    if (t < 144) s_db[t] = dep_b[t];

    int kbase = (sidx == 0 ? 128 : 384) + n * 16;
    int vbase = (sidx == 0 ? 256 : 512) + n * 16;
    const float* Ob = g_OUT + b * 640 * HW;

    // --- load k raw tile ---
    for (int i = t; i < 16 * 324; i += 256) {
        int d  = i / 324;
        int r  = i % 324;
        int iy = r / 18, ix = r % 18;
        int yy = ty0 - 1 + iy, xx = tx0 - 1 + ix;
        float v = 0.0f;
        if (yy >= 0 && yy < HH && xx >= 0 && xx < WW)
            v = Ob[(kbase + d) * HW + yy * WW + xx];
        s_raw[d][iy * 20 + ix] = v;
    }
    __syncthreads();

    float logit[9];
#pragma unroll
    for (int a = 0; a < 9; a++) logit[a] = 0.0f;

#pragma unroll 4
    for (int d = 0; d < 16; d++) {
        float qd = Ob[(n * 16 + d) * HW + Y * WW + X];
        float tap[9];
#pragma unroll
        for (int ky = 0; ky < 3; ky++)
#pragma unroll
            for (int kx = 0; kx < 3; kx++)
                tap[ky * 3 + kx] = s_raw[d][(ly + ky) * 20 + lx + kx];
#pragma unroll
        for (int a = 0; a < 9; a++) {
            float kda = s_db[d * 9 + a];
#pragma unroll
            for (int k = 0; k < 9; k++) kda += s_dw[d * 9 + a][k] * tap[k];
            logit[a] += qd * kda;
        }
    }

    // softmax over 9
    float m = logit[0];
#pragma unroll
    for (int a = 1; a < 9; a++) m = fmaxf(m, logit[a]);
    float attn[9];
    float sum = 0.0f;
#pragma unroll
    for (int a = 0; a < 9; a++) { attn[a] = __expf(logit[a] - m); sum += attn[a]; }
    float inv = 1.0f / sum;
#pragma unroll
    for (int a = 0; a < 9; a++) attn[a] *= inv;

    __syncthreads();
    // --- load v raw tile ---
    for (int i = t; i < 16 * 324; i += 256) {
        int d  = i / 324;
        int r  = i % 324;
        int iy = r / 18, ix = r % 18;
        int yy = ty0 - 1 + iy, xx = tx0 - 1 + ix;
        float v = 0.0f;
        if (yy >= 0 && yy < HH && xx >= 0 && xx < WW)
            v = Ob[(vbase + d) * HW + yy * WW + xx];
        s_raw[d][iy * 20 + ix] = v;
    }
    __syncthreads();

    float* outp = g_ATT + ((b * 2 + sidx) * DIM + n * 16) * HW + Y * WW + X;
#pragma unroll 4
    for (int d = 0; d < 16; d++) {
        float tap[9];
#pragma unroll
        for (int ky = 0; ky < 3; ky++)
#pragma unroll
            for (int kx = 0; kx < 3; kx++)
                tap[ky * 3 + kx] = s_raw[d][(ly + ky) * 20 + lx + kx];
        float outd = 0.0f;
#pragma unroll
        for (int a = 0; a < 9; a++) {
            float vda = s_db[d * 9 + a];
#pragma unroll
            for (int k = 0; k < 9; k++) vda += s_dw[d * 9 + a][k] * tap[k];
            outd += attn[a] * vda;
        }
        outp[d * HW] = outd;
    }
}

// ---------------------------------------------------------------------------
// 1x1 projection: 64 pixels x 128 oc per block
// ---------------------------------------------------------------------------
__global__ __launch_bounds__(256) void proj_kernel(const float* __restrict__ wt,
                                                   const float* __restrict__ bias,
                                                   int sidx, float* __restrict__ out)
{
    __shared__ float s_w[32][128];
    __shared__ float s_in[32][64];

    int b  = blockIdx.y;
    int p0 = blockIdx.x * 64;
    int t  = threadIdx.x;
    int pg = t & 31;   // 32 pixel-pair groups
    int og = t >> 5;   // 8 oc groups of 16

    float acc0[16], acc1[16];
#pragma unroll
    for (int o = 0; o < 16; o++) { acc0[o] = 0.0f; acc1[o] = 0.0f; }

    const float* inb = g_ATT + (b * 2 + sidx) * DIM * HW;

    for (int c0 = 0; c0 < 128; c0 += 32) {
        for (int i = t; i < 32 * 128; i += 256) {
            int cc = i >> 7;
            int oc = i & 127;
            s_w[cc][oc] = wt[oc * 128 + c0 + cc];
        }
        for (int i = t; i < 32 * 64; i += 256) {
            int cc = i >> 6;
            int pp = i & 63;
            s_in[cc][pp] = inb[(c0 + cc) * HW + p0 + pp];
        }
        __syncthreads();
#pragma unroll
        for (int cc = 0; cc < 32; cc++) {
            float i0 = s_in[cc][pg * 2];
            float i1 = s_in[cc][pg * 2 + 1];
#pragma unroll
            for (int o = 0; o < 16; o++) {
                float wv = s_w[cc][og * 16 + o];
                acc0[o] += i0 * wv;
                acc1[o] += i1 * wv;
            }
        }
        __syncthreads();
    }
#pragma unroll
    for (int o = 0; o < 16; o++) {
        int oc = og * 16 + o;
        float bs = bias[oc];
        out[(b * 128 + oc) * HW + p0 + pg * 2]     = acc0[o] + bs;
        out[(b * 128 + oc) * HW + p0 + pg * 2 + 1] = acc1[o] + bs;
    }
}

// ---------------------------------------------------------------------------
extern "C" void kernel_launch(void* const* d_in, const int* in_sizes, int n_in,
                              void* d_out, int out_size)
{
    const float* x        = (const float*)d_in[0];
    const float* ms       = (const float*)d_in[1];
    const float* lpan     = (const float*)d_in[2];
    const float* pan      = (const float*)d_in[3];
    const float* s        = (const float*)d_in[4];
    const float* q_w      = (const float*)d_in[5];
    const float* q_b      = (const float*)d_in[6];
    const float* k_pan_w  = (const float*)d_in[7];
    const float* k_pan_b  = (const float*)d_in[8];
    const float* v_pan_w  = (const float*)d_in[9];
    const float* v_pan_b  = (const float*)d_in[10];
    const float* kv_ms_w  = (const float*)d_in[11];
    const float* kv_ms_b  = (const float*)d_in[12];
    const float* dep_w    = (const float*)d_in[13];
    const float* dep_b    = (const float*)d_in[14];
    const float* ppan_w   = (const float*)d_in[15];
    const float* ppan_b   = (const float*)d_in[16];
    const float* pms_w    = (const float*)d_in[17];
    const float* pms_b    = (const float*)d_in[18];
    float* out = (float*)d_out;

    const float SCALE = 0.25f;   // HD^-0.5 = 16^-0.5

    pack_kernel<<<(BB * HW + 255) / 256, 256>>>(ms, lpan, pan, s);

    dim3 cg(64, 4, BB);
    conv3x3_kernel<<<cg, 256>>>(x, q_w,     q_b,     136, 0,  0,   SCALE);
    conv3x3_kernel<<<cg, 256>>>(x, k_pan_w, k_pan_b, 129, 8,  128, 1.0f);
    conv3x3_kernel<<<cg, 256>>>(x, v_pan_w, v_pan_b, 131, 8,  256, 1.0f);
    dim3 cg2(64, 8, BB);
    conv3x3_kernel<<<cg2, 256>>>(x, kv_ms_w, kv_ms_b, 136, 11, 384, 1.0f);

    dim3 ag(64, 16, BB);
    attn_kernel<<<ag, 256>>>(dep_w, dep_b);

    dim3 pg(HW / 64, BB);
    proj_kernel<<<pg, 256>>>(ppan_w, ppan_b, 0, out);
    proj_kernel<<<pg, 256>>>(pms_w,  pms_b,  1, out + BB * DIM * HW);
}